// round 12
// baseline (speedup 1.0000x reference)
#include <cuda_runtime.h>
#include <cstdint>

#define BB      256
#define LL      512
#define DD      64
#define NID     10000
#define NSTORE  2048        // store-role CTAs in kernel 1
#define NT      512

// Exception list: one u32 per non-mode output row.
//   bits [0:10)  row within batch: 0..511 = src rows, 512..1023 = dst rows
//   bits [10:20) a0 (count in src seq), bits [20:30) a1 (count in dst seq)
__device__ uint32_t exc_buf[BB * 2 * LL];   // worst case: every row exceptional
__device__ uint32_t exc_cnt[BB];

// ---------------------------------------------------------------------------
// Kernel 1: blocks [0,2048) blast the mode row g(0)+g(1) over the whole
// output (pure STG.128 stream). Blocks [2048,2304) build per-batch packed
// histograms (lo16 = count in src seq, hi16 = in dst seq) and emit the
// exception list. Hist blocks are the last bids -> overlap the store tail.
// ---------------------------------------------------------------------------
__global__ void __launch_bounds__(NT) blast_and_hist(
        const int* __restrict__ src,
        const int* __restrict__ dst,
        const float* __restrict__ W1,
        const float* __restrict__ b1,
        const float* __restrict__ W2,
        const float* __restrict__ b2,
        float* __restrict__ out) {
    __shared__ __align__(16) uint32_t sm[NID];   // hist | (store: wm floats)
    __shared__ uint32_t s_cnt;
    const int t = threadIdx.x;

    if (blockIdx.x < NSTORE) {
        // ---------------- store role ----------------
        float* wm = (float*)sm;                  // 64 floats: g(0)[e]+g(1)[e]
        if (t < DD) {
            const int e = t;
            float s0 = __ldg(&b2[e]);            // accumulates g(0)[e]
            float s1 = s0;                       // accumulates g(1)[e]
            const float4* w14 = (const float4*)W1;
            const float4* b14 = (const float4*)b1;
            const float4* w24 = (const float4*)(W2 + e * DD);
            #pragma unroll 4
            for (int j = 0; j < 16; ++j) {
                const float4 w1v = __ldg(&w14[j]);
                const float4 b1v = __ldg(&b14[j]);
                const float4 w2v = __ldg(&w24[j]);
                // a = 0 row: h = relu(fmaf(0, w1, b1))
                s0 = fmaf(fmaxf(fmaf(0.f, w1v.x, b1v.x), 0.f), w2v.x, s0);
                s0 = fmaf(fmaxf(fmaf(0.f, w1v.y, b1v.y), 0.f), w2v.y, s0);
                s0 = fmaf(fmaxf(fmaf(0.f, w1v.z, b1v.z), 0.f), w2v.z, s0);
                s0 = fmaf(fmaxf(fmaf(0.f, w1v.w, b1v.w), 0.f), w2v.w, s0);
                // a = 1 row
                s1 = fmaf(fmaxf(fmaf(1.f, w1v.x, b1v.x), 0.f), w2v.x, s1);
                s1 = fmaf(fmaxf(fmaf(1.f, w1v.y, b1v.y), 0.f), w2v.y, s1);
                s1 = fmaf(fmaxf(fmaf(1.f, w1v.z, b1v.z), 0.f), w2v.z, s1);
                s1 = fmaf(fmaxf(fmaf(1.f, w1v.w, b1v.w), 0.f), w2v.w, s1);
            }
            wm[e] = s0 + s1;
        }
        __syncthreads();

        const float4 wmv = ((const float4*)wm)[t & 15];
        float4* __restrict__ o4 = (float4*)out;
        const size_t g4 = (size_t)blockIdx.x * (NT * 4) + t;
        #pragma unroll
        for (int it = 0; it < 4; ++it)
            o4[g4 + it * NT] = wmv;
        return;
    }

    // ---------------- histogram role ----------------
    const int b = blockIdx.x - NSTORE;
    const uint4 z = make_uint4(0u, 0u, 0u, 0u);
    #pragma unroll
    for (int i = t; i < NID / 4; i += NT) ((uint4*)sm)[i] = z;
    if (t == 0) s_cnt = 0u;

    const int sid = src[b * LL + t];
    const int did = dst[b * LL + t];
    __syncthreads();

    atomicAdd(&sm[sid], 1u);
    atomicAdd(&sm[did], 0x10000u);
    __syncthreads();

    const uint32_t hs = sid ? sm[sid] : 0u;     // padding id 0 -> (0,0)
    const uint32_t hd = did ? sm[did] : 0u;
    if (hs != 1u) {                             // src mode is (a0,a1) = (1,0)
        const uint32_t i = atomicAdd(&s_cnt, 1u);
        exc_buf[b * (2 * LL) + i] =
            (uint32_t)t | ((hs & 0xFFFFu) << 10) | ((hs >> 16) << 20);
    }
    if (hd != 0x10000u) {                       // dst mode is (a0,a1) = (0,1)
        const uint32_t i = atomicAdd(&s_cnt, 1u);
        exc_buf[b * (2 * LL) + i] =
            (uint32_t)(t + LL) | ((hd & 0xFFFFu) << 10) | ((hd >> 16) << 20);
    }
    __syncthreads();
    if (t == 0) exc_cnt[b] = s_cnt;
}

// ---------------------------------------------------------------------------
// Kernel 2: fix up exception rows. One CTA per batch; 8x64 g-table in smem
// (one entry per thread); each 16-lane group rewrites one exception row.
// ---------------------------------------------------------------------------
__global__ void __launch_bounds__(NT) fixup(
        const int* __restrict__ src,   // unused, kept for uniform signature
        const float* __restrict__ W1,
        const float* __restrict__ b1,
        const float* __restrict__ W2,
        const float* __restrict__ b2,
        float* __restrict__ out) {
    __shared__ __align__(16) float g8[8 * DD];
    const int t = threadIdx.x;
    const int b = blockIdx.x;

    // build g-table rows 0..7 (one entry per thread)
    {
        const int a = t >> 6, e = t & 63;
        const float fa = (float)a;
        float s = __ldg(&b2[e]);
        const float4* w14 = (const float4*)W1;
        const float4* b14 = (const float4*)b1;
        const float4* w24 = (const float4*)(W2 + e * DD);
        #pragma unroll 4
        for (int j = 0; j < 16; ++j) {
            const float4 w1v = __ldg(&w14[j]);
            const float4 b1v = __ldg(&b14[j]);
            const float4 w2v = __ldg(&w24[j]);
            s = fmaf(fmaxf(fmaf(fa, w1v.x, b1v.x), 0.f), w2v.x, s);
            s = fmaf(fmaxf(fmaf(fa, w1v.y, b1v.y), 0.f), w2v.y, s);
            s = fmaf(fmaxf(fmaf(fa, w1v.z, b1v.z), 0.f), w2v.z, s);
            s = fmaf(fmaxf(fmaf(fa, w1v.w, b1v.w), 0.f), w2v.w, s);
        }
        g8[t] = s;
    }
    __syncthreads();

    const uint32_t n = exc_cnt[b];
    const int lane = t & 15;
    const float4* __restrict__ G4 = (const float4*)g8;
    float4* __restrict__ o4 = (float4*)out;

    for (uint32_t i = (uint32_t)(t >> 4); i < n; i += 32) {
        const uint32_t u   = exc_buf[b * (2 * LL) + i];
        const uint32_t row = u & 1023u;
        const uint32_t a0  = (u >> 10) & 1023u;
        const uint32_t a1  = u >> 20;
        float4 v;
        if (a0 < 8u && a1 < 8u) {
            const float4 v0 = G4[a0 * 16 + lane];
            const float4 v1 = G4[a1 * 16 + lane];
            v.x = v0.x + v1.x; v.y = v0.y + v1.y;
            v.z = v0.z + v1.z; v.w = v0.w + v1.w;
        } else {
            // rare/never path: direct compute for large counts
            const float fa0 = (float)a0, fa1 = (float)a1;
            v.x = 2.f * __ldg(&b2[lane * 4 + 0]);
            v.y = 2.f * __ldg(&b2[lane * 4 + 1]);
            v.z = 2.f * __ldg(&b2[lane * 4 + 2]);
            v.w = 2.f * __ldg(&b2[lane * 4 + 3]);
            for (int d = 0; d < DD; ++d) {
                const float w1d = __ldg(&W1[d]), b1d = __ldg(&b1[d]);
                const float h = fmaxf(fmaf(fa0, w1d, b1d), 0.f)
                              + fmaxf(fmaf(fa1, w1d, b1d), 0.f);
                v.x = fmaf(h, __ldg(&W2[(lane * 4 + 0) * DD + d]), v.x);
                v.y = fmaf(h, __ldg(&W2[(lane * 4 + 1) * DD + d]), v.y);
                v.z = fmaf(h, __ldg(&W2[(lane * 4 + 2) * DD + d]), v.z);
                v.w = fmaf(h, __ldg(&W2[(lane * 4 + 3) * DD + d]), v.w);
            }
        }
        const size_t orow = (row < LL)
            ? ((size_t)b * LL + row)                    // src block
            : ((size_t)(BB + b) * LL + (row - LL));     // dst block
        o4[orow * 16 + lane] = v;
    }
}

// ---------------------------------------------------------------------------
// Inputs: 0 src_ids, 1 dst_ids, 2 W1(D,1), 3 b1(D), 4 W2(D,D), 5 b2(D)
// Output: [src_feat | dst_feat], each B*L*D f32.
// ---------------------------------------------------------------------------
extern "C" void kernel_launch(void* const* d_in, const int* in_sizes, int n_in,
                              void* d_out, int out_size) {
    const int*   src = (const int*)d_in[0];
    const int*   dst = (const int*)d_in[1];
    const float* W1  = (const float*)d_in[2];
    const float* b1  = (const float*)d_in[3];
    const float* W2  = (const float*)d_in[4];
    const float* b2  = (const float*)d_in[5];
    float* out = (float*)d_out;

    blast_and_hist<<<NSTORE + BB, NT>>>(src, dst, W1, b1, W2, b2, out);
    fixup<<<BB, NT>>>(src, W1, b1, W2, b2, out);
}

// round 13
// speedup vs baseline: 1.2793x; 1.2793x over previous
#include <cuda_runtime.h>
#include <cstdint>

#define BB  256
#define LL  512
#define DD  64
#define NID 10000
#define TMAX 32          // smem table rows (counts beyond take the uniform cold path)

// dynamic smem layout (bytes):
//   [0      , 16384) W2s    : 64x64 f32
//   [16384  , 24576) table  : 32x64 f32   (g(a) rows, a in [0, nrows))
//   [24576  , 32768) h_all  : 32x64 f32   (relu(a*w1+b1) rows)
//   [32768  , 34816) cs     : 512 u32 packed (src_cnt | dst_cnt<<16) per src pos
//   [34816  , 36864) cd     : 512 u32 per dst pos
//   [36864  , 76864) hist   : 10000 u32 (lo16 = count in src, hi16 = count in dst)
//   [76864  , 76868) maxc
#define SMEM_BYTES 76880

__global__ void __launch_bounds__(512, 2) fused_encode(
        const int* __restrict__ src,
        const int* __restrict__ dst,
        const float* __restrict__ W1,
        const float* __restrict__ b1,
        const float* __restrict__ W2,
        const float* __restrict__ b2,
        float* __restrict__ out) {
    extern __shared__ unsigned char sraw[];
    float*    W2s   = (float*)(sraw);
    float*    table = (float*)(sraw + 16384);
    float*    h_all = (float*)(sraw + 24576);
    uint32_t* cs    = (uint32_t*)(sraw + 32768);
    uint32_t* cd    = (uint32_t*)(sraw + 34816);
    uint32_t* hist  = (uint32_t*)(sraw + 36864);
    uint32_t* maxc  = (uint32_t*)(sraw + 76864);

    const int t = threadIdx.x;
    const int b = blockIdx.x;

    // --- phase 0: zero histogram (128-bit), stage W2 into smem, load ids ---
    const uint4 z = make_uint4(0u, 0u, 0u, 0u);
    #pragma unroll
    for (int i = t; i < NID / 4; i += 512) ((uint4*)hist)[i] = z;
    if (t == 0) *maxc = 0u;
    #pragma unroll
    for (int i = t; i < (DD * DD) / 4; i += 512)
        ((float4*)W2s)[i] = ((const float4*)W2)[i];

    const int sid = src[b * LL + t];
    const int did = dst[b * LL + t];
    __syncthreads();

    // --- phase 1: packed dual histogram ---
    atomicAdd(&hist[sid], 1u);
    atomicAdd(&hist[did], 0x10000u);
    __syncthreads();

    // --- phase 2: gather per-position counts, find max count in this batch ---
    const uint32_t hs = sid ? hist[sid] : 0u;   // padding id 0 -> (0,0)
    const uint32_t hd = did ? hist[did] : 0u;
    cs[t] = hs;
    cd[t] = hd;
    uint32_t m = max(max(hs & 0xFFFFu, hs >> 16), max(hd & 0xFFFFu, hd >> 16));
    m = __reduce_max_sync(0xFFFFFFFFu, m);
    if ((t & 31) == 0) atomicMax(maxc, m);
    __syncthreads();

    const int nrows = min((int)(*maxc) + 1, TMAX);
    const bool direct = ((int)(*maxc) + 1) > TMAX;   // CTA-uniform, never true here

    // --- phase 3: build g-table rows 0..nrows-1 in smem (two-step, as R2) ---
    for (int idx = t; idx < nrows * DD; idx += 512) {
        const int a = idx >> 6, d = idx & 63;
        const float hv = fmaf((float)a, W1[d], b1[d]);
        h_all[idx] = hv > 0.f ? hv : 0.f;
    }
    __syncthreads();
    for (int idx = t; idx < nrows * DD; idx += 512) {
        const int a = idx >> 6, e = idx & 63;
        float s = b2[e];
        const float* hr = h_all + a * DD;
        const float* wr = W2s + e * DD;
        #pragma unroll 16
        for (int d = 0; d < DD; ++d) s = fmaf(hr[d], wr[d], s);
        table[idx] = s;
    }
    __syncthreads();

    // --- phase 4: streamed, float4-coalesced output. 16 lanes per 64-f row,
    // 512 threads cover 32 rows/iter, 16 iters for L=512. ---
    const int lane = t & 15;
    const float4* T4 = (const float4*)table;
    float4* __restrict__ osrc = (float4*)(out + (size_t)b * LL * DD);
    float4* __restrict__ odst = (float4*)(out + (size_t)BB * LL * DD
                                              + (size_t)b * LL * DD);

    if (!direct) {
        #pragma unroll 2
        for (int r = (t >> 4); r < LL; r += 32) {
            uint32_t c = cs[r];
            float4 v0 = T4[(c & 0xFFFFu) * 16 + lane];
            float4 v1 = T4[(c >> 16)    * 16 + lane];
            float4 w;
            w.x = v0.x + v1.x; w.y = v0.y + v1.y;
            w.z = v0.z + v1.z; w.w = v0.w + v1.w;
            osrc[r * 16 + lane] = w;

            c = cd[r];
            v0 = T4[(c & 0xFFFFu) * 16 + lane];
            v1 = T4[(c >> 16)    * 16 + lane];
            w.x = v0.x + v1.x; w.y = v0.y + v1.y;
            w.z = v0.z + v1.z; w.w = v0.w + v1.w;
            odst[r * 16 + lane] = w;
        }
    } else {
        // CTA-uniform cold path (never taken with this data): direct compute.
        for (int r = (t >> 4); r < LL; r += 32) {
            const uint32_t c0 = cs[r], c1 = cd[r];
            const float sa0 = (float)(c0 & 0xFFFFu), sa1 = (float)(c0 >> 16);
            const float da0 = (float)(c1 & 0xFFFFu), da1 = (float)(c1 >> 16);
            float4 accs, accd;
            accs.x = 2.f * b2[lane * 4 + 0]; accd.x = accs.x;
            accs.y = 2.f * b2[lane * 4 + 1]; accd.y = accs.y;
            accs.z = 2.f * b2[lane * 4 + 2]; accd.z = accs.z;
            accs.w = 2.f * b2[lane * 4 + 3]; accd.w = accs.w;
            for (int d = 0; d < DD; ++d) {
                const float w1d = W1[d], b1d = b1[d];
                const float hss = fmaxf(fmaf(sa0, w1d, b1d), 0.f)
                                + fmaxf(fmaf(sa1, w1d, b1d), 0.f);
                const float hdd = fmaxf(fmaf(da0, w1d, b1d), 0.f)
                                + fmaxf(fmaf(da1, w1d, b1d), 0.f);
                accs.x = fmaf(hss, W2s[(lane*4+0)*DD + d], accs.x);
                accs.y = fmaf(hss, W2s[(lane*4+1)*DD + d], accs.y);
                accs.z = fmaf(hss, W2s[(lane*4+2)*DD + d], accs.z);
                accs.w = fmaf(hss, W2s[(lane*4+3)*DD + d], accs.w);
                accd.x = fmaf(hdd, W2s[(lane*4+0)*DD + d], accd.x);
                accd.y = fmaf(hdd, W2s[(lane*4+1)*DD + d], accd.y);
                accd.z = fmaf(hdd, W2s[(lane*4+2)*DD + d], accd.z);
                accd.w = fmaf(hdd, W2s[(lane*4+3)*DD + d], accd.w);
            }
            osrc[r * 16 + lane] = accs;
            odst[r * 16 + lane] = accd;
        }
    }
}

// ---------------------------------------------------------------------------
// Inputs: 0 src_ids, 1 dst_ids, 2 W1(D,1), 3 b1(D), 4 W2(D,D), 5 b2(D)
// Output: [src_feat | dst_feat], each B*L*D f32.
// ---------------------------------------------------------------------------
extern "C" void kernel_launch(void* const* d_in, const int* in_sizes, int n_in,
                              void* d_out, int out_size) {
    const int*   src = (const int*)d_in[0];
    const int*   dst = (const int*)d_in[1];
    const float* W1  = (const float*)d_in[2];
    const float* b1  = (const float*)d_in[3];
    const float* W2  = (const float*)d_in[4];
    const float* b2  = (const float*)d_in[5];
    float* out = (float*)d_out;

    cudaFuncSetAttribute(fused_encode,
                         cudaFuncAttributeMaxDynamicSharedMemorySize, SMEM_BYTES);
    fused_encode<<<BB, 512, SMEM_BYTES>>>(src, dst, W1, b1, W2, b2, out);
}

// round 14
// speedup vs baseline: 1.7617x; 1.3771x over previous
#include <cuda_runtime.h>
#include <cstdint>

#define BB  256
#define LL  512
#define DD  64
#define NID 10000
#define TMAX 32          // smem table rows (counts beyond this take the direct path)

// dynamic smem layout (bytes):
//   [0      , 16384) W2s    : 64x64 f32
//   [16384  , 24576) table  : 32x64 f32   (g(a) rows, a in [0, nrows))
//   [24576  , 32768) h_all  : 32x64 f32   (relu(a*w1+b1) rows)
//   [32768  , 34816) cs     : 512 u32 packed (src_cnt | dst_cnt<<16) per src pos
//   [34816  , 36864) cd     : 512 u32 per dst pos
//   [36864  , 76864) hist   : 10000 u32 (lo16 = count in src, hi16 = count in dst)
//   [76864  , 76868) maxc
#define SMEM_BYTES 76880

// Direct computation of g(a)[e..e+3] for the (never-in-practice) case a >= nrows.
__device__ __forceinline__ float4 g_direct(uint32_t a, int lane,
                                           const float* __restrict__ W1,
                                           const float* __restrict__ b1,
                                           const float* __restrict__ b2,
                                           const float* __restrict__ W2s) {
    float4 s = ((const float4*)b2)[lane];
    const int e = lane * 4;
    for (int d = 0; d < DD; ++d) {
        float hv = fmaf((float)a, W1[d], b1[d]);
        hv = hv > 0.f ? hv : 0.f;
        s.x = fmaf(hv, W2s[(e + 0) * DD + d], s.x);
        s.y = fmaf(hv, W2s[(e + 1) * DD + d], s.y);
        s.z = fmaf(hv, W2s[(e + 2) * DD + d], s.z);
        s.w = fmaf(hv, W2s[(e + 3) * DD + d], s.w);
    }
    return s;
}

__global__ void __launch_bounds__(512, 2) fused_encode(
        const int* __restrict__ src,
        const int* __restrict__ dst,
        const float* __restrict__ W1,
        const float* __restrict__ b1,
        const float* __restrict__ W2,
        const float* __restrict__ b2,
        float* __restrict__ out) {
    extern __shared__ unsigned char sraw[];
    float*    W2s   = (float*)(sraw);
    float*    table = (float*)(sraw + 16384);
    float*    h_all = (float*)(sraw + 24576);
    uint32_t* cs    = (uint32_t*)(sraw + 32768);
    uint32_t* cd    = (uint32_t*)(sraw + 34816);
    uint32_t* hist  = (uint32_t*)(sraw + 36864);
    uint32_t* maxc  = (uint32_t*)(sraw + 76864);

    const int t = threadIdx.x;
    const int b = blockIdx.x;

    // --- phase 0: zero histogram (128-bit), stage W2 into smem, load ids ---
    const uint4 z = make_uint4(0u, 0u, 0u, 0u);
    #pragma unroll
    for (int i = t; i < NID / 4; i += 512) ((uint4*)hist)[i] = z;
    if (t == 0) *maxc = 0u;
    #pragma unroll
    for (int i = t; i < (DD * DD) / 4; i += 512)
        ((float4*)W2s)[i] = ((const float4*)W2)[i];

    const int sid = src[b * LL + t];
    const int did = dst[b * LL + t];
    __syncthreads();

    // --- phase 1: packed dual histogram ---
    atomicAdd(&hist[sid], 1u);
    atomicAdd(&hist[did], 0x10000u);
    __syncthreads();

    // --- phase 2: gather per-position counts, find max count in this batch ---
    const uint32_t hs = sid ? hist[sid] : 0u;   // padding id 0 -> (0,0)
    const uint32_t hd = did ? hist[did] : 0u;
    cs[t] = hs;
    cd[t] = hd;
    uint32_t m = max(max(hs & 0xFFFFu, hs >> 16), max(hd & 0xFFFFu, hd >> 16));
    m = __reduce_max_sync(0xFFFFFFFFu, m);
    if ((t & 31) == 0) atomicMax(maxc, m);
    __syncthreads();

    const int nrows = min((int)(*maxc) + 1, TMAX);

    // --- phase 3: build g-table rows 0..nrows-1 in smem ---
    for (int idx = t; idx < nrows * DD; idx += 512) {
        const int a = idx >> 6, d = idx & 63;
        const float hv = fmaf((float)a, W1[d], b1[d]);
        h_all[idx] = hv > 0.f ? hv : 0.f;
    }
    __syncthreads();
    for (int idx = t; idx < nrows * DD; idx += 512) {
        const int a = idx >> 6, e = idx & 63;
        float s = b2[e];
        const float* hr = h_all + a * DD;
        const float* wr = W2s + e * DD;
        #pragma unroll 16
        for (int d = 0; d < DD; ++d) s = fmaf(hr[d], wr[d], s);
        table[idx] = s;
    }
    __syncthreads();

    // --- phase 4: streamed, float4-coalesced output. 16 lanes per 64-f row,
    // 512 threads cover 32 rows/iter, 16 iters for L=512. ---
    const int lane = t & 15;
    const float4* T4 = (const float4*)table;
    float4* __restrict__ osrc = (float4*)(out + (size_t)b * LL * DD);
    float4* __restrict__ odst = (float4*)(out + (size_t)BB * LL * DD
                                              + (size_t)b * LL * DD);

    for (int r = (t >> 4); r < LL; r += 32) {
        uint32_t c = cs[r];
        uint32_t a0 = c & 0xFFFFu, a1 = c >> 16;
        float4 v0 = (a0 < (uint32_t)nrows) ? T4[a0 * 16 + lane]
                                           : g_direct(a0, lane, W1, b1, b2, W2s);
        float4 v1 = (a1 < (uint32_t)nrows) ? T4[a1 * 16 + lane]
                                           : g_direct(a1, lane, W1, b1, b2, W2s);
        float4 w;
        w.x = v0.x + v1.x; w.y = v0.y + v1.y;
        w.z = v0.z + v1.z; w.w = v0.w + v1.w;
        osrc[r * 16 + lane] = w;

        c = cd[r];
        a0 = c & 0xFFFFu; a1 = c >> 16;
        v0 = (a0 < (uint32_t)nrows) ? T4[a0 * 16 + lane]
                                    : g_direct(a0, lane, W1, b1, b2, W2s);
        v1 = (a1 < (uint32_t)nrows) ? T4[a1 * 16 + lane]
                                    : g_direct(a1, lane, W1, b1, b2, W2s);
        w.x = v0.x + v1.x; w.y = v0.y + v1.y;
        w.z = v0.z + v1.z; w.w = v0.w + v1.w;
        odst[r * 16 + lane] = w;
    }
}

extern "C" void kernel_launch(void* const* d_in, const int* in_sizes, int n_in,
                              void* d_out, int out_size) {
    const int*   src = (const int*)d_in[0];
    const int*   dst = (const int*)d_in[1];
    const float* W1  = (const float*)d_in[2];
    const float* b1  = (const float*)d_in[3];
    const float* W2  = (const float*)d_in[4];
    const float* b2  = (const float*)d_in[5];
    float* out = (float*)d_out;

    cudaFuncSetAttribute(fused_encode,
                         cudaFuncAttributeMaxDynamicSharedMemorySize, SMEM_BYTES);
    fused_encode<<<BB, 512, SMEM_BYTES>>>(src, dst, W1, b1, W2, b2, out);
}

// round 15
// speedup vs baseline: 1.8109x; 1.0279x over previous
#include <cuda_runtime.h>
#include <cstdint>

#define BB  256
#define LL  512
#define DD  64
#define NID 10000
#define TMAX 32          // smem table rows (counts beyond this take the direct path)

// dynamic smem layout (bytes):
//   [0      , 16384) W2s    : 64x64 f32; REUSED after phase 3 as comb[64][64]
//   [16384  , 24576) table  : 32x64 f32   (g(a) rows, a in [0, nrows))
//   [24576  , 32768) h_all  : 32x64 f32   (relu(a*w1+b1) rows)
//   [32768  , 34816) cs     : 512 u32 packed (src_cnt | dst_cnt<<16) per src pos
//   [34816  , 36864) cd     : 512 u32 per dst pos
//   [36864  , 76864) hist   : 10000 u32 (lo16 = count in src, hi16 = count in dst)
//   [76864  , 76868) maxc
#define SMEM_BYTES 76880

// Direct computation of g(a)[e..e+3] for the (never-in-practice) case where the
// combined table doesn't cover (a0,a1). Reads W2 from global (W2s is reused).
__device__ __forceinline__ float4 g_direct(uint32_t a, int lane,
                                           const float* __restrict__ W1,
                                           const float* __restrict__ b1,
                                           const float* __restrict__ b2,
                                           const float* __restrict__ W2) {
    float4 s = ((const float4*)b2)[lane];
    const int e = lane * 4;
    for (int d = 0; d < DD; ++d) {
        float hv = fmaf((float)a, W1[d], b1[d]);
        hv = hv > 0.f ? hv : 0.f;
        s.x = fmaf(hv, __ldg(&W2[(e + 0) * DD + d]), s.x);
        s.y = fmaf(hv, __ldg(&W2[(e + 1) * DD + d]), s.y);
        s.z = fmaf(hv, __ldg(&W2[(e + 2) * DD + d]), s.z);
        s.w = fmaf(hv, __ldg(&W2[(e + 3) * DD + d]), s.w);
    }
    return s;
}

__global__ void __launch_bounds__(512, 2) fused_encode(
        const int* __restrict__ src,
        const int* __restrict__ dst,
        const float* __restrict__ W1,
        const float* __restrict__ b1,
        const float* __restrict__ W2,
        const float* __restrict__ b2,
        float* __restrict__ out) {
    extern __shared__ unsigned char sraw[];
    float*    W2s   = (float*)(sraw);            // later: comb[64][64]
    float*    table = (float*)(sraw + 16384);
    float*    h_all = (float*)(sraw + 24576);
    uint32_t* cs    = (uint32_t*)(sraw + 32768);
    uint32_t* cd    = (uint32_t*)(sraw + 34816);
    uint32_t* hist  = (uint32_t*)(sraw + 36864);
    uint32_t* maxc  = (uint32_t*)(sraw + 76864);

    const int t = threadIdx.x;
    const int b = blockIdx.x;

    // --- phase 0: zero histogram (128-bit), stage W2 into smem, load ids ---
    const uint4 z = make_uint4(0u, 0u, 0u, 0u);
    #pragma unroll
    for (int i = t; i < NID / 4; i += 512) ((uint4*)hist)[i] = z;
    if (t == 0) *maxc = 0u;
    #pragma unroll
    for (int i = t; i < (DD * DD) / 4; i += 512)
        ((float4*)W2s)[i] = ((const float4*)W2)[i];

    const int sid = src[b * LL + t];
    const int did = dst[b * LL + t];
    __syncthreads();

    // --- phase 1: packed dual histogram ---
    atomicAdd(&hist[sid], 1u);
    atomicAdd(&hist[did], 0x10000u);
    __syncthreads();

    // --- phase 2: gather per-position counts, find max count in this batch ---
    const uint32_t hs = sid ? hist[sid] : 0u;   // padding id 0 -> (0,0)
    const uint32_t hd = did ? hist[did] : 0u;
    cs[t] = hs;
    cd[t] = hd;
    uint32_t m = max(max(hs & 0xFFFFu, hs >> 16), max(hd & 0xFFFFu, hd >> 16));
    m = __reduce_max_sync(0xFFFFFFFFu, m);
    if ((t & 31) == 0) atomicMax(maxc, m);
    __syncthreads();

    const int nrows = min((int)(*maxc) + 1, TMAX);

    // --- phase 3: build g-table rows 0..nrows-1 in smem ---
    for (int idx = t; idx < nrows * DD; idx += 512) {
        const int a = idx >> 6, d = idx & 63;
        const float hv = fmaf((float)a, W1[d], b1[d]);
        h_all[idx] = hv > 0.f ? hv : 0.f;
    }
    __syncthreads();
    for (int idx = t; idx < nrows * DD; idx += 512) {
        const int a = idx >> 6, e = idx & 63;
        float s = b2[e];
        const float* hr = h_all + a * DD;
        const float* wr = W2s + e * DD;
        #pragma unroll 16
        for (int d = 0; d < DD; ++d) s = fmaf(hr[d], wr[d], s);
        table[idx] = s;
    }
    __syncthreads();

    // --- phase 3b: combined pair table over the dead W2s region.
    // comb[a0 + 8*a1][e] = table[a0][e] + table[a1][e]; covers all rows when
    // counts < 8 (the practical case). Bit-identical to adding per row. ---
    float* comb = W2s;
    #pragma unroll
    for (int i = t; i < 64 * DD; i += 512) {
        const int e  = i & 63;
        const int a0 = (i >> 6) & 7;
        const int a1 = i >> 9;
        comb[i] = table[a0 * DD + e] + table[a1 * DD + e];
    }
    __syncthreads();

    // --- phase 4: streamed, float4-coalesced output. 16 lanes per 64-f row,
    // 512 threads cover 32 rows/iter, 16 iters for L=512. Hot element:
    // 1 LDS.128 (combined row) + 1 STG.128, no arithmetic. ---
    const int lane = t & 15;
    const float4* C4 = (const float4*)comb;
    float4* __restrict__ osrc = (float4*)(out + (size_t)b * LL * DD);
    float4* __restrict__ odst = (float4*)(out + (size_t)BB * LL * DD
                                              + (size_t)b * LL * DD);

    for (int r = (t >> 4); r < LL; r += 32) {
        uint32_t c = cs[r];
        float4 w;
        if ((c & 0xFFF8FFF8u) == 0u) {          // both counts < 8 -> comb row
            const uint32_t pair = (c & 7u) + ((c >> 16) << 3);
            w = C4[pair * 16 + lane];
        } else {
            const float4 v0 = g_direct(c & 0xFFFFu, lane, W1, b1, b2, W2);
            const float4 v1 = g_direct(c >> 16,     lane, W1, b1, b2, W2);
            w.x = v0.x + v1.x; w.y = v0.y + v1.y;
            w.z = v0.z + v1.z; w.w = v0.w + v1.w;
        }
        osrc[r * 16 + lane] = w;

        c = cd[r];
        if ((c & 0xFFF8FFF8u) == 0u) {
            const uint32_t pair = (c & 7u) + ((c >> 16) << 3);
            w = C4[pair * 16 + lane];
        } else {
            const float4 v0 = g_direct(c & 0xFFFFu, lane, W1, b1, b2, W2);
            const float4 v1 = g_direct(c >> 16,     lane, W1, b1, b2, W2);
            w.x = v0.x + v1.x; w.y = v0.y + v1.y;
            w.z = v0.z + v1.z; w.w = v0.w + v1.w;
        }
        odst[r * 16 + lane] = w;
    }
}

extern "C" void kernel_launch(void* const* d_in, const int* in_sizes, int n_in,
                              void* d_out, int out_size) {
    const int*   src = (const int*)d_in[0];
    const int*   dst = (const int*)d_in[1];
    const float* W1  = (const float*)d_in[2];
    const float* b1  = (const float*)d_in[3];
    const float* W2  = (const float*)d_in[4];
    const float* b2  = (const float*)d_in[5];
    float* out = (float*)d_out;

    cudaFuncSetAttribute(fused_encode,
                         cudaFuncAttributeMaxDynamicSharedMemorySize, SMEM_BYTES);
    fused_encode<<<BB, 512, SMEM_BYTES>>>(src, dst, W1, b1, W2, b2, out);
}